// round 17
// baseline (speedup 1.0000x reference)
#include <cuda_runtime.h>
#include <cuda_fp16.h>
#include <math.h>

// ---------------------------------------------------------------------------
// Problem constants
// ---------------------------------------------------------------------------
#define NN   50000      // nodes
#define NE   1600000    // edges
#define HID  128
#define NG   500        // graphs
#define SLOPE 0.3f
#define BN_EPS 1e-5f
#define LOG2E 1.44269504f
#define RED_SCALE 262144.0f          // 2^18 fixed-point scale for int redux
#define RED_INV   (1.0f / 262144.0f)

// ---------------------------------------------------------------------------
// Device scratch (no allocation allowed).
// deg is zeroed at the TAIL of each call (zero-initialized at module load for
// call 1), so every call observes it zeroed on entry. cursor is fully
// overwritten by scan_add2 each call (no zeroing needed).
// ---------------------------------------------------------------------------
__device__ __half g_xlh[NN * HID];     // fp16 message features (gather-heavy)
__device__ float  g_xr[NN * HID];
__device__ float  g_h1[NN * HID];
__device__ float  g_h2[NN * HID];
__device__ int    g_deg[NN];
__device__ int    g_cursor[NN + 1];
__device__ int    g_rowstart[NN + 1];
__device__ int    g_bsums[64];
__device__ int    g_csr_src[NE];
__device__ float  g_score[NN];
__device__ float  g_gsum[NG];
__device__ float  g_pooled[NG * HID];

// ---------------------------------------------------------------------------
// TF32 GEMM building blocks
// ---------------------------------------------------------------------------
__device__ __forceinline__ unsigned int tf32cvt(float f) {
    unsigned int u;
    asm("cvt.rna.tf32.f32 %0, %1;" : "=r"(u) : "f"(f));
    return u;
}

__device__ __forceinline__ void mma16n8k8(float4& d, const unsigned int a[4],
                                          unsigned int b0, unsigned int b1) {
    asm volatile(
        "mma.sync.aligned.m16n8k8.row.col.f32.tf32.tf32.f32 "
        "{%0,%1,%2,%3}, {%4,%5,%6,%7}, {%8,%9}, {%0,%1,%2,%3};"
        : "+f"(d.x), "+f"(d.y), "+f"(d.z), "+f"(d.w)
        : "r"(a[0]), "r"(a[1]), "r"(a[2]), "r"(a[3]), "r"(b0), "r"(b1));
}

#define ASTRIDE 36
#define BSTRIDE 136

__device__ __forceinline__ void gemm_mainloop(
        const float* __restrict__ A, const float* __restrict__ W,
        float* As, float* Bs, float4 acc[2][8],
        int rowBase, int n, int tid, int g, int tg, int warpM, int warpN) {
    for (int k0 = 0; k0 < 128; k0 += 32) {
#pragma unroll
        for (int it = 0; it < 4; it++) {
            int idx = tid + it * 256;
            int row = idx >> 3, k4 = idx & 7;
            int grow = rowBase + row;
            float4 v = make_float4(0.f, 0.f, 0.f, 0.f);
            if (grow < n) v = *(const float4*)(A + (size_t)grow * 128 + k0 + k4 * 4);
            float4 t;
            t.x = __uint_as_float(tf32cvt(v.x));
            t.y = __uint_as_float(tf32cvt(v.y));
            t.z = __uint_as_float(tf32cvt(v.z));
            t.w = __uint_as_float(tf32cvt(v.w));
            *(float4*)&As[row * ASTRIDE + k4 * 4] = t;
        }
#pragma unroll
        for (int it = 0; it < 4; it++) {
            int idx = tid + it * 256;
            int k = idx >> 5, n4 = idx & 31;
            float4 v = *(const float4*)(W + (size_t)(k0 + k) * 128 + n4 * 4);
            float4 t;
            t.x = __uint_as_float(tf32cvt(v.x));
            t.y = __uint_as_float(tf32cvt(v.y));
            t.z = __uint_as_float(tf32cvt(v.z));
            t.w = __uint_as_float(tf32cvt(v.w));
            *(float4*)&Bs[k * BSTRIDE + n4 * 4] = t;
        }
        __syncthreads();

#pragma unroll
        for (int kk = 0; kk < 4; kk++) {
            unsigned int bfr[8][2];
#pragma unroll
            for (int nt = 0; nt < 8; nt++) {
                int col = warpN + nt * 8 + g;
                bfr[nt][0] = __float_as_uint(Bs[(kk * 8 + tg) * BSTRIDE + col]);
                bfr[nt][1] = __float_as_uint(Bs[(kk * 8 + tg + 4) * BSTRIDE + col]);
            }
#pragma unroll
            for (int mt = 0; mt < 2; mt++) {
                int r0 = warpM + mt * 16 + g;
                unsigned int a[4];
                a[0] = __float_as_uint(As[r0 * ASTRIDE + kk * 8 + tg]);
                a[1] = __float_as_uint(As[(r0 + 8) * ASTRIDE + kk * 8 + tg]);
                a[2] = __float_as_uint(As[r0 * ASTRIDE + kk * 8 + tg + 4]);
                a[3] = __float_as_uint(As[(r0 + 8) * ASTRIDE + kk * 8 + tg + 4]);
#pragma unroll
                for (int nt = 0; nt < 8; nt++)
                    mma16n8k8(acc[mt][nt], a, bfr[nt][0], bfr[nt][1]);
            }
        }
        __syncthreads();
    }
}

// ---------------------------------------------------------------------------
// Device-side GEMM epilogues (shared by fused + standalone kernels)
// ---------------------------------------------------------------------------
__device__ __forceinline__ void gemm_dual_body(
        const float* __restrict__ A,
        const float* __restrict__ Wl, const float* __restrict__ Wr,
        __half* __restrict__ xlh, float* __restrict__ xr, int n,
        int bx, int nb, float* As, float* Bs) {
    int tid = threadIdx.x;
    int wid = tid >> 5, lane = tid & 31;
    int g = lane >> 2, tg = lane & 3;
    int warpM = (wid >> 1) * 32;
    int warpN = (wid & 1) * 64;
    bool left = (bx < nb);
    int rowBase = (left ? bx : bx - nb) * 128;
    const float* W = left ? Wl : Wr;

    float4 acc[2][8];
#pragma unroll
    for (int mt = 0; mt < 2; mt++)
#pragma unroll
        for (int nt = 0; nt < 8; nt++) acc[mt][nt] = make_float4(0.f, 0.f, 0.f, 0.f);

    gemm_mainloop(A, W, As, Bs, acc, rowBase, n, tid, g, tg, warpM, warpN);

    if (left) {
#pragma unroll
        for (int mt = 0; mt < 2; mt++) {
#pragma unroll
            for (int nt = 0; nt < 8; nt++) {
                int c0 = warpN + nt * 8 + tg * 2;
                int r0 = rowBase + warpM + mt * 16 + g;
                float4 d = acc[mt][nt];
                if (r0 < n)
                    *(__half2*)(xlh + (size_t)r0 * 128 + c0) = __floats2half2_rn(d.x, d.y);
                if (r0 + 8 < n)
                    *(__half2*)(xlh + (size_t)(r0 + 8) * 128 + c0) = __floats2half2_rn(d.z, d.w);
            }
        }
    } else {
#pragma unroll
        for (int mt = 0; mt < 2; mt++) {
#pragma unroll
            for (int nt = 0; nt < 8; nt++) {
                int c0 = warpN + nt * 8 + tg * 2;
                int r0 = rowBase + warpM + mt * 16 + g;
                float4 d = acc[mt][nt];
                if (r0 < n)     *(float2*)(xr + (size_t)r0 * 128 + c0) = make_float2(d.x, d.y);
                if (r0 + 8 < n) *(float2*)(xr + (size_t)(r0 + 8) * 128 + c0) = make_float2(d.z, d.w);
            }
        }
    }
}

// ---------------------------------------------------------------------------
// FUSED: layer-1 dual GEMM + count_deg in ONE launch (no data dependency;
// blocks run concurrently => total ~= max, not sum).
//   blockIdx.x < 2*nb          : dual GEMM path
//   blockIdx.x >= 2*nb         : 4-edges-per-thread degree histogram
// ---------------------------------------------------------------------------
__global__ __launch_bounds__(256) void gemm1_count_kernel(
        const float* __restrict__ A,
        const float* __restrict__ Wl, const float* __restrict__ Wr,
        __half* __restrict__ xlh, float* __restrict__ xr, int n, int nb,
        const int* __restrict__ dst, int* __restrict__ deg, int e) {
    __shared__ float As[128 * ASTRIDE];
    __shared__ float Bs[32 * BSTRIDE];
    int gemmBlocks = 2 * nb;
    if ((int)blockIdx.x < gemmBlocks) {
        gemm_dual_body(A, Wl, Wr, xlh, xr, n, blockIdx.x, nb, As, Bs);
    } else {
        int i = ((blockIdx.x - gemmBlocks) * blockDim.x + threadIdx.x) * 4;
        if (i + 3 < e) {
            int4 d = *(const int4*)(dst + i);
            atomicAdd(&deg[d.x], 1);
            atomicAdd(&deg[d.y], 1);
            atomicAdd(&deg[d.z], 1);
            atomicAdd(&deg[d.w], 1);
        } else {
            for (; i < e; i++) atomicAdd(&deg[dst[i]], 1);
        }
    }
}

// ---------------------------------------------------------------------------
// Standalone dual GEMM (layer 2)
// ---------------------------------------------------------------------------
__global__ __launch_bounds__(256) void gemm_dual_kernel(
        const float* __restrict__ A,
        const float* __restrict__ Wl, const float* __restrict__ Wr,
        __half* __restrict__ xlh, float* __restrict__ xr, int n, int nb) {
    __shared__ float As[128 * ASTRIDE];
    __shared__ float Bs[32 * BSTRIDE];
    gemm_dual_body(A, Wl, Wr, xlh, xr, n, blockIdx.x, nb, As, Bs);
}

// ---------------------------------------------------------------------------
// CSR scan + fill
// ---------------------------------------------------------------------------
__global__ __launch_bounds__(1024) void scan_block_kernel(
        const int* __restrict__ deg, int* __restrict__ rowstart,
        int* __restrict__ bsums, int n) {
    __shared__ int buf[1024];
    int t = threadIdx.x;
    int i = blockIdx.x * 1024 + t;
    int v = (i < n) ? deg[i] : 0;
    buf[t] = v;
    __syncthreads();
#pragma unroll
    for (int off = 1; off < 1024; off <<= 1) {
        int add = (t >= off) ? buf[t - off] : 0;
        __syncthreads();
        buf[t] += add;
        __syncthreads();
    }
    if (i < n) rowstart[i + 1] = buf[t];
    if (t == 1023) bsums[blockIdx.x] = buf[1023];
    if (i == 0) rowstart[0] = 0;
}

__global__ void scan_add2_kernel(int* __restrict__ rowstart,
                                 int* __restrict__ cursor,
                                 const int* __restrict__ bsums, int n) {
    __shared__ int soff;
    int t = threadIdx.x;
    int bid = blockIdx.x;          // 256 elements per block; 1024 % 256 == 0
    int b = bid >> 2;              // which 1024-chunk => bsums prefix length
    if (t == 0) soff = 0;
    __syncthreads();
    if (t < b) atomicAdd(&soff, bsums[t]);   // b <= 48 < blockDim
    __syncthreads();
    int i = bid * 256 + t;
    if (i < n) {
        int v = rowstart[i + 1] + ((b > 0) ? soff : 0);
        if (b > 0) rowstart[i + 1] = v;
        cursor[i + 1] = v;
        if (i == 0) cursor[0] = 0;
    }
}

__global__ void fill_csr_kernel(const int* __restrict__ src, const int* __restrict__ dst,
                                int* __restrict__ cursor,
                                int* __restrict__ csr_src, int e) {
    int i = (blockIdx.x * blockDim.x + threadIdx.x) * 4;
    if (i + 3 < e) {
        int4 d = *(const int4*)(dst + i);
        int4 s = *(const int4*)(src + i);
        int p0 = atomicAdd(&cursor[d.x], 1);
        int p1 = atomicAdd(&cursor[d.y], 1);
        int p2 = atomicAdd(&cursor[d.z], 1);
        int p3 = atomicAdd(&cursor[d.w], 1);
        csr_src[p0] = s.x;
        csr_src[p1] = s.y;
        csr_src[p2] = s.z;
        csr_src[p3] = s.w;
    } else {
        for (; i < e; i++) {
            int pos = atomicAdd(&cursor[dst[i]], 1);
            csr_src[pos] = src[i];
        }
    }
}

// ---------------------------------------------------------------------------
// Gate GEMM: score[row] = sum_c tanh((h2@Wg1)[row,c]+bg1[c]) * Wg2[c]
// ---------------------------------------------------------------------------
__global__ __launch_bounds__(256) void gemm_gate_kernel(
        const float* __restrict__ A, const float* __restrict__ W,
        const float* __restrict__ bias, const float* __restrict__ Wg2,
        float* __restrict__ score, int n) {
    __shared__ float As[128 * ASTRIDE];
    __shared__ float Bs[32 * BSTRIDE];
    __shared__ float sscore[128];

    int tid = threadIdx.x;
    int wid = tid >> 5, lane = tid & 31;
    int g = lane >> 2, tg = lane & 3;
    int warpM = (wid >> 1) * 32;
    int warpN = (wid & 1) * 64;
    int rowBase = blockIdx.x * 128;

    if (tid < 128) sscore[tid] = 0.f;

    float4 acc[2][8];
#pragma unroll
    for (int mt = 0; mt < 2; mt++)
#pragma unroll
        for (int nt = 0; nt < 8; nt++) acc[mt][nt] = make_float4(0.f, 0.f, 0.f, 0.f);

    gemm_mainloop(A, W, As, Bs, acc, rowBase, n, tid, g, tg, warpM, warpN);

    float rp[2][2] = {{0.f, 0.f}, {0.f, 0.f}};
#pragma unroll
    for (int mt = 0; mt < 2; mt++) {
#pragma unroll
        for (int nt = 0; nt < 8; nt++) {
            int c0 = warpN + nt * 8 + tg * 2;
            float4 d = acc[mt][nt];
            float w0 = Wg2[c0], w1 = Wg2[c0 + 1];
            float b0 = bias[c0], b1 = bias[c0 + 1];
            rp[mt][0] += tanhf(d.x + b0) * w0 + tanhf(d.y + b1) * w1;
            rp[mt][1] += tanhf(d.z + b0) * w0 + tanhf(d.w + b1) * w1;
        }
        atomicAdd(&sscore[warpM + mt * 16 + g], rp[mt][0]);
        atomicAdd(&sscore[warpM + mt * 16 + g + 8], rp[mt][1]);
    }
    __syncthreads();
    if (tid < 128) {
        int row = rowBase + tid;
        if (row < n) score[row] = sscore[tid];
    }
}

// ---------------------------------------------------------------------------
// GATv2 aggregation: one warp per destination node, batch-6 edges.
// NON-STABLE softmax, half2 score arithmetic, log2e folded -> bare exp2f.
// GROUP==32: fixed-point s32 __reduce_add_sync (REDUX).
// ---------------------------------------------------------------------------
template <int GROUP>
__device__ __forceinline__ float group_reduce(float v) {
    if (GROUP == 32) {
        int vi = __float2int_rn(v * RED_SCALE);
        int si = __reduce_add_sync(0xffffffffu, vi);
        return (float)si * RED_INV;
    } else {
        v += __shfl_xor_sync(0xffffffffu, v, 1);
        v += __shfl_xor_sync(0xffffffffu, v, 2);
        return v;
    }
}

template <int GROUP>
__global__ __launch_bounds__(256) void gat_agg_kernel(
        const __half* __restrict__ xlh, const float* __restrict__ xr,
        const float* __restrict__ att, const float* __restrict__ bias,
        const float* __restrict__ bn_g, const float* __restrict__ bn_b,
        const float* __restrict__ bn_rm, const float* __restrict__ bn_rv,
        const int* __restrict__ rowstart, const int* __restrict__ csr_src,
        float* __restrict__ out, int n) {
    int w = (blockIdx.x * blockDim.x + threadIdx.x) >> 5;
    if (w >= n) return;
    int lane = threadIdx.x & 31;
    int j = lane * 4;

    float4 r4 = *(const float4*)(xr + (size_t)w * 128 + j);
    float4 a4 = *(const float4*)(att + j);
    __half2 r0h = __floats2half2_rn(r4.x, r4.y);
    __half2 r1h = __floats2half2_rn(r4.z, r4.w);
    __half2 a0h = __floats2half2_rn(a4.x * LOG2E, a4.y * LOG2E);
    __half2 a1h = __floats2half2_rn(a4.z * LOG2E, a4.w * LOG2E);
    const __half2 sl2 = __floats2half2_rn(SLOPE, SLOPE);

    int e0 = rowstart[w], e1 = rowstart[w + 1];
    float s = 0.f;
    float4 acc = make_float4(0.f, 0.f, 0.f, 0.f);

    auto score_h2 = [&](__half2 l0, __half2 l1) {
        __half2 t0 = __hadd2(l0, r0h);
        __half2 t1 = __hadd2(l1, r1h);
        t0 = __hmax2(t0, __hmul2(t0, sl2));   // leaky relu (slope<1)
        t1 = __hmax2(t1, __hmul2(t1, sl2));
        __half2 d2 = __hfma2(t0, a0h, __hmul2(t1, a1h));
        float2 f = __half22float2(d2);
        return group_reduce<GROUP>(f.x + f.y);
    };

    int e = e0;
#pragma unroll 1
    for (; e + 5 < e1; e += 6) {
        float2 wv[6];
#pragma unroll
        for (int q = 0; q < 6; q++) {
            int sq = csr_src[e + q];
            wv[q] = *(const float2*)(xlh + (size_t)sq * 128 + j);
        }
        float p[6];
#pragma unroll
        for (int q = 0; q < 6; q++) {
            __half2 l0 = *(__half2*)&wv[q].x, l1 = *(__half2*)&wv[q].y;
            p[q] = exp2f(score_h2(l0, l1));
        }
        s += ((p[0] + p[1]) + (p[2] + p[3])) + (p[4] + p[5]);
#pragma unroll
        for (int q = 0; q < 6; q++) {
            __half2 l0 = *(__half2*)&wv[q].x, l1 = *(__half2*)&wv[q].y;
            float2 f0 = __half22float2(l0);
            float2 f1 = __half22float2(l1);
            acc.x = fmaf(p[q], f0.x, acc.x);
            acc.y = fmaf(p[q], f0.y, acc.y);
            acc.z = fmaf(p[q], f1.x, acc.z);
            acc.w = fmaf(p[q], f1.y, acc.w);
        }
    }
#pragma unroll 1
    for (; e < e1; e++) {
        int sa = csr_src[e];
        float2 wv = *(const float2*)(xlh + (size_t)sa * 128 + j);
        __half2 l0 = *(__half2*)&wv.x, l1 = *(__half2*)&wv.y;
        float p = exp2f(score_h2(l0, l1));
        s += p;
        float2 f0 = __half22float2(l0);
        float2 f1 = __half22float2(l1);
        acc.x = fmaf(p, f0.x, acc.x);
        acc.y = fmaf(p, f0.y, acc.y);
        acc.z = fmaf(p, f1.x, acc.z);
        acc.w = fmaf(p, f1.y, acc.w);
    }

    float inv = 1.0f / (s + 1e-16f);
    float4 bi = *(const float4*)(bias + j);
    float4 gg = *(const float4*)(bn_g + j);
    float4 bb = *(const float4*)(bn_b + j);
    float4 rm = *(const float4*)(bn_rm + j);
    float4 rv = *(const float4*)(bn_rv + j);

    float4 o;
    o.x = acc.x * inv + bi.x;
    o.y = acc.y * inv + bi.y;
    o.z = acc.z * inv + bi.z;
    o.w = acc.w * inv + bi.w;
    o.x = fmaxf(0.f, (o.x - rm.x) * (gg.x * rsqrtf(rv.x + BN_EPS)) + bb.x);
    o.y = fmaxf(0.f, (o.y - rm.y) * (gg.y * rsqrtf(rv.y + BN_EPS)) + bb.y);
    o.z = fmaxf(0.f, (o.z - rm.z) * (gg.z * rsqrtf(rv.z + BN_EPS)) + bb.z);
    o.w = fmaxf(0.f, (o.w - rm.w) * (gg.w * rsqrtf(rv.w + BN_EPS)) + bb.w);
    *(float4*)(out + (size_t)w * 128 + j) = o;
}

// ---------------------------------------------------------------------------
// Fused exp + weighted pool: warp per node, lane-parallel conflict-free atomics
// ---------------------------------------------------------------------------
__global__ __launch_bounds__(256) void pool_fused_kernel(
        const float* __restrict__ h2, const float* __restrict__ score,
        const int* __restrict__ batch,
        float* __restrict__ gsum, float* __restrict__ pooled, int n) {
    int w = (blockIdx.x * blockDim.x + threadIdx.x) >> 5;
    if (w >= n) return;
    int lane = threadIdx.x & 31;
    int j = lane * 4;
    int g = batch[w];
    float wv = __expf(score[w]);
    if (lane == 0) atomicAdd(&gsum[g], wv);
    float4 h = *(const float4*)(h2 + (size_t)w * 128 + j);
    float* base = pooled + (size_t)g * 128 + j;
    atomicAdd(base + 0, wv * h.x);
    atomicAdd(base + 1, wv * h.y);
    atomicAdd(base + 2, wv * h.z);
    atomicAdd(base + 3, wv * h.w);
}

// ---------------------------------------------------------------------------
// fc head: relu((pooled/gsum) @ Wf1 + bf1) @ Wf2 + bf2   -> out[g]
// ---------------------------------------------------------------------------
__global__ __launch_bounds__(128) void fc_head_kernel(
        const float* __restrict__ pooled, const float* __restrict__ gsum,
        const float* __restrict__ Wf1, const float* __restrict__ bf1,
        const float* __restrict__ Wf2, const float* __restrict__ bf2,
        float* __restrict__ out) {
    int g = blockIdx.x;
    int t = threadIdx.x;
    __shared__ float sp[128];
    __shared__ float red[128];
    float inv = 1.0f / (gsum[g] + 1e-16f);
    sp[t] = pooled[(size_t)g * 128 + t] * inv;
    __syncthreads();
    float contrib = 0.f;
    if (t < 100) {
        float acc = bf1[t];
#pragma unroll 8
        for (int k = 0; k < 128; k++) acc = fmaf(sp[k], Wf1[k * 100 + t], acc);
        contrib = fmaxf(acc, 0.f) * Wf2[t];
    }
    red[t] = contrib;
    __syncthreads();
    for (int off = 64; off > 0; off >>= 1) {
        if (t < off) red[t] += red[t + off];
        __syncthreads();
    }
    if (t == 0) out[g] = red[0] + bf2[0];
}

// ---------------------------------------------------------------------------
// Host driver — single stream; count_deg hidden under layer-1 GEMM (one launch)
// ---------------------------------------------------------------------------
extern "C" void kernel_launch(void* const* d_in, const int* in_sizes, int n_in,
                              void* d_out, int out_size) {
    const float* x    = (const float*)d_in[0];
    const int*   ei   = (const int*)d_in[1];
    const int*   batch= (const int*)d_in[2];
    const float* Wl1  = (const float*)d_in[3];
    const float* Wr1  = (const float*)d_in[4];
    const float* att1 = (const float*)d_in[5];
    const float* b1   = (const float*)d_in[6];
    const float* Wl2  = (const float*)d_in[7];
    const float* Wr2  = (const float*)d_in[8];
    const float* att2 = (const float*)d_in[9];
    const float* b2   = (const float*)d_in[10];
    const float* bn_g = (const float*)d_in[11];
    const float* bn_b = (const float*)d_in[12];
    const float* bn_rm= (const float*)d_in[13];
    const float* bn_rv= (const float*)d_in[14];
    const float* Wg1  = (const float*)d_in[15];
    const float* bg1  = (const float*)d_in[16];
    const float* Wg2  = (const float*)d_in[17];
    const float* Wf1  = (const float*)d_in[18];
    const float* bf1  = (const float*)d_in[19];
    const float* Wf2  = (const float*)d_in[20];
    const float* bf2  = (const float*)d_in[21];

    const int n = in_sizes[0] / HID;      // 50000
    const int e = in_sizes[1] / 2;        // 1600000
    const int ng = out_size;              // 500
    const int* src = ei;
    const int* dst = ei + e;

    float *xr, *h1, *h2, *score, *gsum, *pooled;
    __half* xlh;
    int *deg, *cursor, *rowstart, *csr_src, *bsums;
    cudaGetSymbolAddress((void**)&xlh, g_xlh);
    cudaGetSymbolAddress((void**)&xr, g_xr);
    cudaGetSymbolAddress((void**)&h1, g_h1);
    cudaGetSymbolAddress((void**)&h2, g_h2);
    cudaGetSymbolAddress((void**)&deg, g_deg);
    cudaGetSymbolAddress((void**)&cursor, g_cursor);
    cudaGetSymbolAddress((void**)&rowstart, g_rowstart);
    cudaGetSymbolAddress((void**)&bsums, g_bsums);
    cudaGetSymbolAddress((void**)&csr_src, g_csr_src);
    cudaGetSymbolAddress((void**)&score, g_score);
    cudaGetSymbolAddress((void**)&gsum, g_gsum);
    cudaGetSymbolAddress((void**)&pooled, g_pooled);

    const int TB = 256;
    int nb = (n + 127) / 128;             // 391 GEMM blocks per projection
    int gemmGrid = nb;
    int warpGrid = (n * 32 + TB - 1) / TB;
    int nScanBlocks = (n + 1023) / 1024;
    int edge4Grid = ((e + 3) / 4 + TB - 1) / TB;

    // ---- FUSED: layer-1 dual GEMM + degree histogram (concurrent blocks) ----
    gemm1_count_kernel<<<2 * nb + edge4Grid, TB>>>(x, Wl1, Wr1, xlh, xr, n, nb,
                                                   dst, deg, e);

    // ---- CSR scan + fill ----
    scan_block_kernel<<<nScanBlocks, 1024>>>(deg, rowstart, bsums, n);
    scan_add2_kernel<<<(n + 255) / 256, 256>>>(rowstart, cursor, bsums, n);
    fill_csr_kernel<<<edge4Grid, TB>>>(src, dst, cursor, csr_src, e);

    // ---- layer 1 aggregation ----
    gat_agg_kernel<4><<<warpGrid, TB>>>(xlh, xr, att1, b1, bn_g, bn_b, bn_rm, bn_rv,
                                        rowstart, csr_src, h1, n);

    // ---- layer 2 ----
    gemm_dual_kernel<<<2 * nb, TB>>>(h1, Wl2, Wr2, xlh, xr, n, nb);
    gat_agg_kernel<32><<<warpGrid, TB>>>(xlh, xr, att2, b2, bn_g, bn_b, bn_rm, bn_rv,
                                         rowstart, csr_src, h2, n);

    // ---- attentional aggregation ----
    cudaMemsetAsync(gsum, 0, ng * sizeof(float));
    cudaMemsetAsync(pooled, 0, ng * HID * sizeof(float));
    gemm_gate_kernel<<<gemmGrid, TB>>>(h2, Wg1, bg1, Wg2, score, n);
    pool_fused_kernel<<<warpGrid, TB>>>(h2, score, batch, gsum, pooled, n);

    // ---- fc head ----
    fc_head_kernel<<<ng, 128>>>(pooled, gsum, Wf1, bf1, Wf2, bf2, (float*)d_out);

    // ---- re-zero deg for the next call (deterministic steady state) ----
    cudaMemsetAsync(deg, 0, n * sizeof(int));
}